// round 2
// baseline (speedup 1.0000x reference)
#include <cuda_runtime.h>
#include <math.h>

#define Tt 32
#define Cc 180
#define Hh 6
#define HDd 30
#define Ff 720
#define NT 512
#define NW 16
#define EPS 1e-5f

// padded smem strides (all coprime with 32 banks for the per-lane row reads)
#define PC 181   // xs/hs row stride
#define PF 721   // hid row stride
#define PD 31    // q/k/v head-dim stride
#define PT 33    // score row stride

// smem layout (floats)
#define SM_X   0
#define SM_H   (Tt*PC)                      // 5792
#define SM_R   (2*Tt*PC)                    // 11584 : union region
#define SM_Q   SM_R
#define SM_K   (SM_Q + Hh*Tt*PD)            // +5952
#define SM_V   (SM_K + Hh*Tt*PD)
#define SM_S   (SM_V + Hh*Tt*PD)
#define SM_ATT_END (SM_S + Hh*Tt*PT)        // region = 24192 floats
#define SM_HID SM_R                         // hid = 32*721 = 23072 floats (union)
#define SM_TOTAL (SM_R + 24192)             // 35776 floats = 143104 B

__global__ void __launch_bounds__(NT, 1) block_kernel(
    const float* __restrict__ x,
    const float* __restrict__ wq, const float* __restrict__ wk, const float* __restrict__ wv,
    const float* __restrict__ g1, const float* __restrict__ be1,
    const float* __restrict__ g2, const float* __restrict__ be2,
    const float* __restrict__ w1, const float* __restrict__ b1,
    const float* __restrict__ w2, const float* __restrict__ b2,
    float* __restrict__ out)
{
    extern __shared__ float sm[];
    float* xs = sm + SM_X;
    float* hs = sm + SM_H;
    float* qs = sm + SM_Q;
    float* ks = sm + SM_K;
    float* vs = sm + SM_V;
    float* ss = sm + SM_S;
    float* hid = sm + SM_HID;

    const int b   = blockIdx.x;
    const int tid = threadIdx.x;
    const int w   = tid >> 5;
    const int ln  = tid & 31;
    const float* xg = x + (size_t)b * (Tt*Cc);

    // ---- load x (coalesced LDG, scatter into padded rows) ----
    for (int i = tid; i < Tt*Cc; i += NT)
        xs[(i/Cc)*PC + (i%Cc)] = xg[i];
    __syncthreads();

    // ---- LN1 ----
    for (int t = w; t < Tt; t += NW) {
        float s = 0.f, s2 = 0.f;
        for (int c = ln; c < Cc; c += 32) { float v = xs[t*PC+c]; s += v; s2 += v*v; }
        #pragma unroll
        for (int o = 16; o; o >>= 1) {
            s  += __shfl_xor_sync(0xffffffffu, s,  o);
            s2 += __shfl_xor_sync(0xffffffffu, s2, o);
        }
        float mu = s * (1.f/Cc);
        float inv = rsqrtf(s2 * (1.f/Cc) - mu*mu + EPS);
        for (int c = ln; c < Cc; c += 32)
            hs[t*PC+c] = (xs[t*PC+c] - mu) * inv * g1[c] + be1[c];
    }
    __syncthreads();

    // ---- QKV: warp job = 6 output cols x all 32 t (lane = t). 90 jobs. ----
    {
        const float* hrow = hs + ln*PC;
        for (int job = w; job < 90; job += NW) {
            int n0  = job*6;
            int mat = n0 / Cc;
            int m0  = n0 - mat*Cc;
            int hh  = m0 / HDd;
            int d0  = m0 - hh*HDd;
            const float* W = (mat==0 ? wq : (mat==1 ? wk : wv)) + hh*(Cc*HDd) + d0;
            float a0=0.f,a1=0.f,a2=0.f,a3=0.f,a4=0.f,a5=0.f;
            #pragma unroll 4
            for (int c = 0; c < Cc; c++) {
                float hv = hrow[c];
                float2 p0 = *(const float2*)(W + c*HDd + 0);
                float2 p1 = *(const float2*)(W + c*HDd + 2);
                float2 p2 = *(const float2*)(W + c*HDd + 4);
                a0 += hv*p0.x; a1 += hv*p0.y;
                a2 += hv*p1.x; a3 += hv*p1.y;
                a4 += hv*p2.x; a5 += hv*p2.y;
            }
            float* dst = (mat==0 ? qs : (mat==1 ? ks : vs)) + hh*(Tt*PD) + ln*PD + d0;
            dst[0]=a0; dst[1]=a1; dst[2]=a2; dst[3]=a3; dst[4]=a4; dst[5]=a5;
        }
    }
    __syncthreads();

    // ---- scores + causal softmax: warp per (h, ti), lane = tj. 192 rows. ----
    for (int row = w; row < Hh*Tt; row += NW) {
        int hh = row >> 5, ti = row & 31;
        const float* qp = qs + hh*(Tt*PD) + ti*PD;
        const float* kp = ks + hh*(Tt*PD) + ln*PD;
        float dot = 0.f;
        #pragma unroll
        for (int d = 0; d < HDd; d++) dot += qp[d] * kp[d];
        dot *= 0.18257418583505537f;
        float val = (ln <= ti) ? dot : -1e30f;
        float m = val;
        #pragma unroll
        for (int o = 16; o; o >>= 1) m = fmaxf(m, __shfl_xor_sync(0xffffffffu, m, o));
        float e = (ln <= ti) ? __expf(val - m) : 0.f;
        float sum = e;
        #pragma unroll
        for (int o = 16; o; o >>= 1) sum += __shfl_xor_sync(0xffffffffu, sum, o);
        ss[hh*(Tt*PT) + ti*PT + ln] = e / sum;
    }
    __syncthreads();

    // ---- attn @ V + residual into xs: 30 jobs (6 cols each), lane = t ----
    for (int job = w; job < 30; job += NW) {
        int n0 = job*6;
        int hh = n0 / HDd;
        int d0 = n0 - hh*HDd;
        const float* sp = ss + hh*(Tt*PT) + ln*PT;
        const float* vp = vs + hh*(Tt*PD) + d0;
        float a0=0.f,a1=0.f,a2=0.f,a3=0.f,a4=0.f,a5=0.f;
        #pragma unroll 4
        for (int s = 0; s < Tt; s++) {
            float av = sp[s];
            const float* vr = vp + s*PD;
            a0 += av*vr[0]; a1 += av*vr[1]; a2 += av*vr[2];
            a3 += av*vr[3]; a4 += av*vr[4]; a5 += av*vr[5];
        }
        float* xr = xs + ln*PC + n0;
        xr[0]+=a0; xr[1]+=a1; xr[2]+=a2; xr[3]+=a3; xr[4]+=a4; xr[5]+=a5;
    }
    __syncthreads();

    // ---- LN2: xs -> hs ----
    for (int t = w; t < Tt; t += NW) {
        float s = 0.f, s2 = 0.f;
        for (int c = ln; c < Cc; c += 32) { float v = xs[t*PC+c]; s += v; s2 += v*v; }
        #pragma unroll
        for (int o = 16; o; o >>= 1) {
            s  += __shfl_xor_sync(0xffffffffu, s,  o);
            s2 += __shfl_xor_sync(0xffffffffu, s2, o);
        }
        float mu = s * (1.f/Cc);
        float inv = rsqrtf(s2 * (1.f/Cc) - mu*mu + EPS);
        for (int c = ln; c < Cc; c += 32)
            hs[t*PC+c] = (xs[t*PC+c] - mu) * inv * g2[c] + be2[c];
    }
    __syncthreads();

    // ---- MLP GEMM1: hid = relu(hs @ w1 + b1). 90 jobs (8 cols each), lane = t ----
    {
        const float* hrow = hs + ln*PC;
        for (int job = w; job < 90; job += NW) {
            int f0 = job*8;
            const float* W = w1 + f0;
            float a0=b1[f0+0],a1=b1[f0+1],a2=b1[f0+2],a3=b1[f0+3];
            float a4=b1[f0+4],a5=b1[f0+5],a6=b1[f0+6],a7=b1[f0+7];
            #pragma unroll 4
            for (int c = 0; c < Cc; c++) {
                float hv = hrow[c];
                float4 pa = *(const float4*)(W + c*Ff + 0);
                float4 pb = *(const float4*)(W + c*Ff + 4);
                a0 += hv*pa.x; a1 += hv*pa.y; a2 += hv*pa.z; a3 += hv*pa.w;
                a4 += hv*pb.x; a5 += hv*pb.y; a6 += hv*pb.z; a7 += hv*pb.w;
            }
            float* dst = hid + ln*PF + f0;
            dst[0]=fmaxf(a0,0.f); dst[1]=fmaxf(a1,0.f); dst[2]=fmaxf(a2,0.f); dst[3]=fmaxf(a3,0.f);
            dst[4]=fmaxf(a4,0.f); dst[5]=fmaxf(a5,0.f); dst[6]=fmaxf(a6,0.f); dst[7]=fmaxf(a7,0.f);
        }
    }
    __syncthreads();

    // ---- MLP GEMM2 + residual -> hs. 30 jobs (6 cols each), lane = t ----
    {
        const float* hrow = hid + ln*PF;
        for (int job = w; job < 30; job += NW) {
            int n0 = job*6;
            const float* W = w2 + n0;
            float a0=0.f,a1=0.f,a2=0.f,a3=0.f,a4=0.f,a5=0.f;
            #pragma unroll 4
            for (int cc = 0; cc < Ff; cc++) {
                float hv = hrow[cc];
                float2 p0 = *(const float2*)(W + cc*Cc + 0);
                float2 p1 = *(const float2*)(W + cc*Cc + 2);
                float2 p2 = *(const float2*)(W + cc*Cc + 4);
                a0 += hv*p0.x; a1 += hv*p0.y;
                a2 += hv*p1.x; a3 += hv*p1.y;
                a4 += hv*p2.x; a5 += hv*p2.y;
            }
            float* dst = hs + ln*PC + n0;
            const float* xr = xs + ln*PC + n0;
            dst[0] = xr[0] + b2[n0+0] + a0;
            dst[1] = xr[1] + b2[n0+1] + a1;
            dst[2] = xr[2] + b2[n0+2] + a2;
            dst[3] = xr[3] + b2[n0+3] + a3;
            dst[4] = xr[4] + b2[n0+4] + a4;
            dst[5] = xr[5] + b2[n0+5] + a5;
        }
    }
    __syncthreads();

    // ---- final coalesced store ----
    float* og = out + (size_t)b * (Tt*Cc);
    for (int i = tid; i < Tt*Cc; i += NT)
        og[i] = hs[(i/Cc)*PC + (i%Cc)];
}

extern "C" void kernel_launch(void* const* d_in, const int* in_sizes, int n_in,
                              void* d_out, int out_size) {
    const float* x   = (const float*)d_in[0];
    const float* wq  = (const float*)d_in[1];
    const float* wk  = (const float*)d_in[2];
    const float* wv  = (const float*)d_in[3];
    const float* g1  = (const float*)d_in[4];
    const float* be1 = (const float*)d_in[5];
    const float* g2  = (const float*)d_in[6];
    const float* be2 = (const float*)d_in[7];
    const float* w1  = (const float*)d_in[8];
    const float* b1  = (const float*)d_in[9];
    const float* w2  = (const float*)d_in[10];
    const float* b2  = (const float*)d_in[11];
    float* out = (float*)d_out;

    const int smem_bytes = SM_TOTAL * sizeof(float);
    cudaFuncSetAttribute(block_kernel, cudaFuncAttributeMaxDynamicSharedMemorySize, smem_bytes);
    block_kernel<<<4096, NT, smem_bytes>>>(x, wq, wk, wv, g1, be1, g2, be2, w1, b1, w2, b2, out);
}

// round 4
// speedup vs baseline: 1.8234x; 1.8234x over previous
#include <cuda_runtime.h>
#include <cuda_bf16.h>
#include <math.h>
#include <stdint.h>

#define Bb 4096
#define Tt 32
#define Cc 180
#define Hh 6
#define HDd 30
#define Ff 720
#define EPS 1e-5f
#define ROWS (Bb*Tt)

// ============================================================================
// Device scratch
// ============================================================================
__device__ float g_X2[(size_t)ROWS * Cc];
__device__ __nv_bfloat16 g_W1HI[768 * 192];   // W1^T [n][k], zero-padded
__device__ __nv_bfloat16 g_W1LO[768 * 192];
__device__ __nv_bfloat16 g_W2HI[192 * 768];   // W2^T [n][k], zero-padded
__device__ __nv_bfloat16 g_W2LO[192 * 768];

// ============================================================================
// helpers
// ============================================================================
__device__ __forceinline__ unsigned smem_u32(const void* p) {
    unsigned a;
    asm("{ .reg .u64 t; cvta.to.shared.u64 t, %1; cvt.u32.u64 %0, t; }" : "=r"(a) : "l"(p));
    return a;
}
__device__ __forceinline__ void ldsm_x4(unsigned* r, unsigned addr) {
    asm volatile("ldmatrix.sync.aligned.m8n8.x4.shared.b16 {%0,%1,%2,%3}, [%4];"
                 : "=r"(r[0]), "=r"(r[1]), "=r"(r[2]), "=r"(r[3]) : "r"(addr));
}
__device__ __forceinline__ void mma16816(float* c, const unsigned* a, const unsigned* b) {
    asm volatile(
        "mma.sync.aligned.m16n8k16.row.col.f32.bf16.bf16.f32 "
        "{%0,%1,%2,%3}, {%4,%5,%6,%7}, {%8,%9}, {%0,%1,%2,%3};"
        : "+f"(c[0]), "+f"(c[1]), "+f"(c[2]), "+f"(c[3])
        : "r"(a[0]), "r"(a[1]), "r"(a[2]), "r"(a[3]), "r"(b[0]), "r"(b[1]));
}
__device__ __forceinline__ void split2(float v0, float v1, unsigned& hp, unsigned& lp) {
    __nv_bfloat16 h0 = __float2bfloat16(v0);
    __nv_bfloat16 l0 = __float2bfloat16(v0 - __bfloat162float(h0));
    __nv_bfloat16 h1 = __float2bfloat16(v1);
    __nv_bfloat16 l1 = __float2bfloat16(v1 - __bfloat162float(h1));
    __nv_bfloat162 hh = __halves2bfloat162(h0, h1);
    __nv_bfloat162 ll = __halves2bfloat162(l0, l1);
    hp = *reinterpret_cast<unsigned*>(&hh);
    lp = *reinterpret_cast<unsigned*>(&ll);
}

// ============================================================================
// Prep kernels
// ============================================================================
__global__ void prep_w1(const float* __restrict__ w1) {
    for (int i = blockIdx.x * blockDim.x + threadIdx.x; i < 768 * 192; i += gridDim.x * blockDim.x) {
        int n = i / 192, k = i % 192;
        float v = (n < Ff && k < Cc) ? w1[(size_t)k * Ff + n] : 0.f;
        __nv_bfloat16 h = __float2bfloat16(v);
        g_W1HI[i] = h;
        g_W1LO[i] = __float2bfloat16(v - __bfloat162float(h));
    }
}
__global__ void prep_w2(const float* __restrict__ w2) {
    for (int i = blockIdx.x * blockDim.x + threadIdx.x; i < 192 * 768; i += gridDim.x * blockDim.x) {
        int n = i / 768, k = i % 768;
        float v = (n < Cc && k < Ff) ? w2[(size_t)k * Cc + n] : 0.f;
        __nv_bfloat16 h = __float2bfloat16(v);
        g_W2HI[i] = h;
        g_W2LO[i] = __float2bfloat16(v - __bfloat162float(h));
    }
}

// ============================================================================
// Kernel 1: LN1 + QKV + causal attention + residual -> g_X2 (R1, proven)
// ============================================================================
#define NT1 256
#define SM_X   0
#define SM_H   (Tt*Cc)
#define SM_Q   (2*Tt*Cc)
#define SM_K   (SM_Q + Hh*Tt*HDd)
#define SM_V   (SM_K + Hh*Tt*HDd)
#define SM_S   (SM_V + Hh*Tt*HDd)
#define SM1_TOTAL (SM_S + Hh*Tt*Tt)

__global__ void __launch_bounds__(NT1, 1) attn_kernel(
    const float* __restrict__ x,
    const float* __restrict__ wq, const float* __restrict__ wk, const float* __restrict__ wv,
    const float* __restrict__ g1, const float* __restrict__ be1)
{
    extern __shared__ float sm[];
    float* xs = sm + SM_X;
    float* hs = sm + SM_H;
    float* qs = sm + SM_Q;
    float* ks = sm + SM_K;
    float* vs = sm + SM_V;
    float* ss = sm + SM_S;

    const int b   = blockIdx.x;
    const int tid = threadIdx.x;
    const int w   = tid >> 5;
    const int ln  = tid & 31;
    const float* xg = x + (size_t)b * (Tt*Cc);

    {
        const float4* xg4 = reinterpret_cast<const float4*>(xg);
        float4* xs4 = reinterpret_cast<float4*>(xs);
        for (int i = tid; i < (Tt*Cc)/4; i += NT1) xs4[i] = xg4[i];
    }
    __syncthreads();

    for (int t = w; t < Tt; t += 8) {
        float s = 0.f, s2 = 0.f;
        for (int c = ln; c < Cc; c += 32) { float v = xs[t*Cc+c]; s += v; s2 += v*v; }
        #pragma unroll
        for (int o = 16; o; o >>= 1) {
            s  += __shfl_xor_sync(0xffffffffu, s,  o);
            s2 += __shfl_xor_sync(0xffffffffu, s2, o);
        }
        float mu = s * (1.f/Cc);
        float inv = rsqrtf(s2 * (1.f/Cc) - mu*mu + EPS);
        for (int c = ln; c < Cc; c += 32)
            hs[t*Cc+c] = (xs[t*Cc+c] - mu) * inv * g1[c] + be1[c];
    }
    __syncthreads();

    for (int job = tid; job < 3*Cc; job += NT1) {
        int mat = job / Cc;
        int n   = job % Cc;
        int hh  = n / HDd, d = n % HDd;
        const float* W = (mat == 0 ? wq : (mat == 1 ? wk : wv)) + hh*(Cc*HDd) + d;
        float a[Tt];
        #pragma unroll
        for (int i = 0; i < Tt; i++) a[i] = 0.f;
        #pragma unroll 4
        for (int c = 0; c < Cc; c++) {
            float wv_ = __ldg(W + c*HDd);
            #pragma unroll
            for (int i = 0; i < Tt; i++) a[i] += hs[i*Cc + c] * wv_;
        }
        float* dst = (mat == 0 ? qs : (mat == 1 ? ks : vs)) + hh*(Tt*HDd) + d;
        #pragma unroll
        for (int i = 0; i < Tt; i++) dst[i*HDd] = a[i];
    }
    __syncthreads();

    for (int row = w; row < Hh*Tt; row += 8) {
        int hh = row >> 5, ti = row & 31;
        const float* qp = qs + hh*(Tt*HDd) + ti*HDd;
        const float* kp = ks + hh*(Tt*HDd) + ln*HDd;
        float dot = 0.f;
        #pragma unroll
        for (int d = 0; d < HDd; d++) dot += qp[d] * kp[d];
        dot *= 0.18257418583505537f;
        float val = (ln <= ti) ? dot : -1e30f;
        float m = val;
        #pragma unroll
        for (int o = 16; o; o >>= 1) m = fmaxf(m, __shfl_xor_sync(0xffffffffu, m, o));
        float e = (ln <= ti) ? __expf(val - m) : 0.f;
        float sum = e;
        #pragma unroll
        for (int o = 16; o; o >>= 1) sum += __shfl_xor_sync(0xffffffffu, sum, o);
        ss[hh*(Tt*Tt) + ti*Tt + ln] = e / sum;
    }
    __syncthreads();

    for (int job = tid; job < 2*Cc; job += NT1) {
        int tg = job / Cc, n = job % Cc;
        int hh = n / HDd, d = n % HDd;
        int t0 = tg * 16;
        const float* vp = vs + hh*(Tt*HDd) + d;
        const float* sp = ss + hh*(Tt*Tt) + t0*Tt;
        float a[16];
        #pragma unroll
        for (int i = 0; i < 16; i++) a[i] = 0.f;
        #pragma unroll 4
        for (int tj = 0; tj < Tt; tj++) {
            float vv = vp[tj*HDd];
            #pragma unroll
            for (int i = 0; i < 16; i++) a[i] += sp[i*Tt + tj] * vv;
        }
        #pragma unroll
        for (int i = 0; i < 16; i++) xs[(t0+i)*Cc + n] += a[i];
    }
    __syncthreads();

    float* og = g_X2 + (size_t)b * (Tt*Cc);
    for (int i = tid; i < Tt*Cc; i += NT1) og[i] = xs[i];
}

// ============================================================================
// Kernel 2: LN2 + MLP via mma.sync bf16 hi/lo 3-MMA split + residual -> out
// ============================================================================
#define NT2 256
// smem byte layout
#define A1HI  0
#define A1LO  51200            // 128 rows * 400B
#define B1HI  102400           // 64 rows * 400B
#define B1LO  128000
#define B2HI  153600           // 192 rows * 144B
#define B2LO  181248
#define SM2_TOTAL 208896

__global__ void __launch_bounds__(NT2, 1) mlp_kernel(
    const float* __restrict__ g2, const float* __restrict__ be2,
    const float* __restrict__ b1, const float* __restrict__ b2,
    float* __restrict__ out)
{
    extern __shared__ char sm2[];
    const unsigned sb = smem_u32(sm2);
    const int tid = threadIdx.x;
    const int w   = tid >> 5;
    const int ln  = tid & 31;
    const int g   = ln >> 2;
    const int ti  = ln & 3;
    const size_t row0 = (size_t)blockIdx.x * 128;

    // ---- LN2 + hi/lo split -> A1 [128][200 bf16, stride 400B] ----
    for (int r = w; r < 128; r += 8) {
        const float* xr = g_X2 + (row0 + r) * Cc;
        float s = 0.f, s2 = 0.f;
        for (int c = ln; c < Cc; c += 32) { float v = xr[c]; s += v; s2 += v*v; }
        #pragma unroll
        for (int o = 16; o; o >>= 1) {
            s  += __shfl_xor_sync(0xffffffffu, s,  o);
            s2 += __shfl_xor_sync(0xffffffffu, s2, o);
        }
        float mu = s * (1.f/Cc);
        float inv = rsqrtf(s2 * (1.f/Cc) - mu*mu + EPS);
        for (int cp = ln; cp < 96; cp += 32) {
            int c0 = cp * 2;
            float v0 = (c0   < Cc) ? (xr[c0]  -mu)*inv*g2[c0]   + be2[c0]   : 0.f;
            float v1 = (c0+1 < Cc) ? (xr[c0+1]-mu)*inv*g2[c0+1] + be2[c0+1] : 0.f;
            unsigned hp, lp;
            split2(v0, v1, hp, lp);
            unsigned off = (unsigned)(r*400 + c0*2);
            *(unsigned*)(sm2 + A1HI + off) = hp;
            *(unsigned*)(sm2 + A1LO + off) = lp;
        }
    }
    __syncthreads();

    float C2[96];
    #pragma unroll
    for (int i = 0; i < 96; i++) C2[i] = 0.f;

    // A fragment ldmatrix address (x4): rows = this warp's 16 rows
    const unsigned a1addr = sb + A1HI + (unsigned)((w*16 + (ln & 15))*400 + (ln >> 4)*16);
    // B fragment x4 address pieces: lanes0-15 hi (k0/k8), lanes16-31 lo
    const int brow = ln & 7;
    const int bk   = ((ln >> 3) & 1) * 16;
    const int bsel = (ln >> 4);           // 0 = hi, 1 = lo

    for (int nt = 0; nt < 12; nt++) {
        // ---- stage B1 tile: 64 n-rows x 192 k (hi+lo) ----
        for (int i = tid; i < 1536; i += NT2) {
            int nn = i / 24, k8 = i % 24;
            unsigned so = (unsigned)(nn*400 + k8*16);
            size_t go = (size_t)(nt*64 + nn)*192 + k8*8;
            *(uint4*)(sm2 + B1HI + so) = *(const uint4*)(g_W1HI + go);
            *(uint4*)(sm2 + B1LO + so) = *(const uint4*)(g_W1LO + go);
        }
        // ---- stage B2 tile: 192 n-rows x 64 k (hi+lo) ----
        for (int i = tid; i < 1536; i += NT2) {
            int nn = i / 8, k8 = i % 8;
            unsigned so = (unsigned)(nn*144 + k8*16);
            size_t go = (size_t)nn*768 + nt*64 + k8*8;
            *(uint4*)(sm2 + B2HI + so) = *(const uint4*)(g_W2HI + go);
            *(uint4*)(sm2 + B2LO + so) = *(const uint4*)(g_W2LO + go);
        }
        __syncthreads();

        // ---- GEMM1: C1[16 x 64] = A1(warp rows) @ B1tile^T ----
        float C1[32];
        #pragma unroll
        for (int i = 0; i < 32; i++) C1[i] = 0.f;
        for (int ka = 0; ka < 12; ka++) {
            unsigned ahi[4], alo[4];
            ldsm_x4(ahi, a1addr + ka*32);
            ldsm_x4(alo, a1addr + (A1LO - A1HI) + ka*32);
            #pragma unroll
            for (int na = 0; na < 8; na++) {
                unsigned bf[4];
                unsigned baddr = sb + B1HI + (unsigned)((na*8 + brow)*400 + ka*32 + bk)
                               + (unsigned)(bsel * (B1LO - B1HI));
                ldsm_x4(bf, baddr);   // bf[0..1]=hi, bf[2..3]=lo
                mma16816(C1 + na*4, ahi, bf);       // Ahi*Bhi
                mma16816(C1 + na*4, alo, bf);       // Alo*Bhi
                mma16816(C1 + na*4, ahi, bf + 2);   // Ahi*Blo
            }
        }

        // ---- epilogue1: bias + relu + split -> A2 fragments (regs) ----
        unsigned a2hi[16], a2lo[16];
        #pragma unroll
        for (int j = 0; j < 4; j++) {
            const float* cA = C1 + (2*j)*4;
            const float* cB = C1 + (2*j+1)*4;
            int colA = nt*64 + 16*j + 2*ti;
            int colB = colA + 8;
            float bA0 = (colA   < Ff) ? __ldg(b1 + colA)     : 0.f;
            float bA1 = (colA+1 < Ff) ? __ldg(b1 + colA + 1) : 0.f;
            float bB0 = (colB   < Ff) ? __ldg(b1 + colB)     : 0.f;
            float bB1 = (colB+1 < Ff) ? __ldg(b1 + colB + 1) : 0.f;
            split2(fmaxf(cA[0]+bA0, 0.f), fmaxf(cA[1]+bA1, 0.f), a2hi[j*4+0], a2lo[j*4+0]);
            split2(fmaxf(cA[2]+bA0, 0.f), fmaxf(cA[3]+bA1, 0.f), a2hi[j*4+1], a2lo[j*4+1]);
            split2(fmaxf(cB[0]+bB0, 0.f), fmaxf(cB[1]+bB1, 0.f), a2hi[j*4+2], a2lo[j*4+2]);
            split2(fmaxf(cB[2]+bB0, 0.f), fmaxf(cB[3]+bB1, 0.f), a2hi[j*4+3], a2lo[j*4+3]);
        }

        // ---- GEMM2 accumulate: C2[16 x 192] += A2 @ B2tile^T ----
        #pragma unroll
        for (int ka = 0; ka < 4; ka++) {
            #pragma unroll
            for (int na = 0; na < 24; na++) {
                unsigned bf[4];
                unsigned baddr = sb + B2HI + (unsigned)((na*8 + brow)*144 + ka*32 + bk)
                               + (unsigned)(bsel * (B2LO - B2HI));
                ldsm_x4(bf, baddr);
                mma16816(C2 + na*4, a2hi + ka*4, bf);
                mma16816(C2 + na*4, a2lo + ka*4, bf);
                mma16816(C2 + na*4, a2hi + ka*4, bf + 2);
            }
        }
        __syncthreads();
    }

    // ---- final: C2 + b2 + residual -> out ----
    {
        size_t rA = row0 + w*16 + g;
        size_t rB = rA + 8;
        #pragma unroll
        for (int na = 0; na < 24; na++) {
            int col = na*8 + 2*ti;
            if (col < Cc) {
                float b20 = __ldg(b2 + col), b21 = __ldg(b2 + col + 1);
                out[rA*Cc + col]     = C2[na*4+0] + b20 + g_X2[rA*Cc + col];
                out[rA*Cc + col + 1] = C2[na*4+1] + b21 + g_X2[rA*Cc + col + 1];
                out[rB*Cc + col]     = C2[na*4+2] + b20 + g_X2[rB*Cc + col];
                out[rB*Cc + col + 1] = C2[na*4+3] + b21 + g_X2[rB*Cc + col + 1];
            }
        }
    }
}

// ============================================================================
// Launch
// ============================================================================
extern "C" void kernel_launch(void* const* d_in, const int* in_sizes, int n_in,
                              void* d_out, int out_size) {
    const float* x   = (const float*)d_in[0];
    const float* wq  = (const float*)d_in[1];
    const float* wk  = (const float*)d_in[2];
    const float* wv  = (const float*)d_in[3];
    const float* g1  = (const float*)d_in[4];
    const float* be1 = (const float*)d_in[5];
    const float* g2  = (const float*)d_in[6];
    const float* be2 = (const float*)d_in[7];
    const float* w1  = (const float*)d_in[8];
    const float* b1  = (const float*)d_in[9];
    const float* w2  = (const float*)d_in[10];
    const float* b2  = (const float*)d_in[11];
    float* out = (float*)d_out;

    cudaFuncSetAttribute(attn_kernel, cudaFuncAttributeMaxDynamicSharedMemorySize,
                         SM1_TOTAL * (int)sizeof(float));
    cudaFuncSetAttribute(mlp_kernel, cudaFuncAttributeMaxDynamicSharedMemorySize,
                         SM2_TOTAL);

    prep_w1<<<148, 256>>>(w1);
    prep_w2<<<148, 256>>>(w2);
    attn_kernel<<<Bb, NT1, SM1_TOTAL * sizeof(float)>>>(x, wq, wk, wv, g1, be1);
    mlp_kernel<<<ROWS / 128, NT2, SM2_TOTAL>>>(g2, be2, b1, b2, out);
}